// round 4
// baseline (speedup 1.0000x reference)
#include <cuda_runtime.h>
#include <cuda_bf16.h>
#include <cstdint>

// ---------------------------------------------------------------------------
// RelGraphEmbedLayer:
//   out[i] = feat0[type_ids[i]] @ W0           if node_tids[i] == 0
//   out[i] = node_embed_table[node_ids[i]]      if node_tids[i] == 1
//
// kA: compaction into payload lists + W0 fragment pre-split (self-resetting)
// kB: fused mma.sync bf16 GEMM (3-pass hi/lo split) + embedding copy,
//     roles interleaved by blockIdx for memory/tensor overlap.
// ---------------------------------------------------------------------------

#define D_IN   256
#define EMBED  128
#define TILE_M 128
#define KCHUNK 32

__device__ int  g_c0, g_c1, g_arrA;
__device__ int2 g_final;
__device__ int2 g_list0[1100000];     // (dst_row, feat0_row)
__device__ int2 g_list1[1100000];     // (dst_row, node_id)
__device__ uint2 g_BH[8192];          // W0 hi frags, layout (ktile*16+tn)*32+lane
__device__ uint2 g_BL[8192];          // W0 lo frags

__device__ __forceinline__ long long load_idx(const void* p, int i, int is64) {
    if (is64) return ((const long long*)p)[i];
    return (long long)((const int*)p)[i];
}

__device__ __forceinline__ void split2(float x, float y, unsigned& hi, unsigned& lo) {
    __nv_bfloat162 h = __floats2bfloat162_rn(x, y);
    float rx = x - __bfloat162float(__low2bfloat16(h));
    float ry = y - __bfloat162float(__high2bfloat16(h));
    __nv_bfloat162 l = __floats2bfloat162_rn(rx, ry);
    hi = *(unsigned*)&h;
    lo = *(unsigned*)&l;
}

__device__ __forceinline__ void mma16816(float* d, const uint4& a, const uint2& b) {
    asm volatile(
        "mma.sync.aligned.m16n8k16.row.col.f32.bf16.bf16.f32 "
        "{%0,%1,%2,%3}, {%4,%5,%6,%7}, {%8,%9}, {%0,%1,%2,%3};"
        : "+f"(d[0]), "+f"(d[1]), "+f"(d[2]), "+f"(d[3])
        : "r"(a.x), "r"(a.y), "r"(a.z), "r"(a.w), "r"(b.x), "r"(b.y));
}

// ---------------------------------------------------------------------------
// kA: blocks [0, cblocks): compaction. blocks [cblocks, cblocks+4): W0 split.
// Last-arriving block publishes counts to g_final and zeroes counters so the
// next graph replay starts clean (no separate reset kernel).
// ---------------------------------------------------------------------------
__global__ __launch_bounds__(256) void kA(
    const void* __restrict__ node_ids,
    const void* __restrict__ node_tids,
    const void* __restrict__ type_ids,
    const float* __restrict__ W0,
    int N, int cblocks, int gridTotal)
{
    const int b = blockIdx.x;
    const int t = threadIdx.x;

    if (b >= cblocks) {
        // ---- W0 -> bf16 hi/lo fragments in mma order ----
        const int wb = b - cblocks;
        for (int f = wb * 256 + t; f < 8192; f += 1024) {
            const int ktile = f >> 9;
            const int tn    = (f >> 5) & 15;
            const int ln    = f & 31;
            const int sg    = ln >> 2;
            const int stc   = ln & 3;
            const int col   = tn * 8 + sg;
            const int krow  = ktile * 16 + stc * 2;
            float b00 = W0[(size_t)krow * EMBED + col];
            float b01 = W0[(size_t)(krow + 1) * EMBED + col];
            float b10 = W0[(size_t)(krow + 8) * EMBED + col];
            float b11 = W0[(size_t)(krow + 9) * EMBED + col];
            uint2 H, L;
            split2(b00, b01, H.x, L.x);
            split2(b10, b11, H.y, L.y);
            g_BH[f] = H;
            g_BL[f] = L;
        }
    } else {
        // ---- compaction with payloads ----
        const unsigned* w = (const unsigned*)node_ids;
        int is64 = 1;
        #pragma unroll
        for (int k = 0; k < 8; ++k)
            if (w[2 * k + 1] != 0u) { is64 = 0; break; }

        const int i    = b * 256 + t;
        const int lane = t & 31;
        const bool valid = i < N;
        long long tv = valid ? load_idx(node_tids, i, is64) : -1;
        const bool is0 = valid && (tv == 0);
        const bool is1 = valid && (tv != 0);

        unsigned m0 = __ballot_sync(0xffffffffu, is0);
        unsigned m1 = __ballot_sync(0xffffffffu, is1);
        int r0 = __popc(m0 & ((1u << lane) - 1u));
        int r1 = __popc(m1 & ((1u << lane) - 1u));
        int b0 = 0, b1 = 0;
        if (lane == 0) {
            if (m0) b0 = atomicAdd(&g_c0, __popc(m0));
            if (m1) b1 = atomicAdd(&g_c1, __popc(m1));
        }
        b0 = __shfl_sync(0xffffffffu, b0, 0);
        b1 = __shfl_sync(0xffffffffu, b1, 0);
        if (is0) {
            int2 e; e.x = i; e.y = (int)load_idx(type_ids, i, is64);
            g_list0[b0 + r0] = e;
        }
        if (is1) {
            int2 e; e.x = i; e.y = (int)load_idx(node_ids, i, is64);
            g_list1[b1 + r1] = e;
        }
    }

    // ---- arrival + self-reset ----
    __syncthreads();
    if (t == 0) {
        __threadfence();
        int old = atomicAdd(&g_arrA, 1);
        if (old == gridTotal - 1) {
            int2 f;
            f.x = atomicAdd(&g_c0, 0);
            f.y = atomicAdd(&g_c1, 0);
            g_final = f;
            g_c0 = 0;
            g_c1 = 0;
            g_arrA = 0;
            __threadfence();
        }
    }
}

// ---------------------------------------------------------------------------
// kB: blockIdx % 8 == 7 -> embed-copy block (e = blockIdx/8, 1024 rows)
//     else              -> GEMM tile go = 7*(blockIdx/8) + blockIdx%8
// GEMM: 128x128x256 tile, 8 warps (2x4), warp tile 64x32, 3-pass hi/lo bf16.
// ---------------------------------------------------------------------------
__global__ __launch_bounds__(256) void kB(
    const float* __restrict__ feat0,
    const float* __restrict__ table,
    float* __restrict__ out)
{
    const int2 counts = g_final;
    const int b = blockIdx.x;
    const int t = threadIdx.x;
    const int e = b >> 3;
    const int r = b & 7;
    const int lane = t & 31;
    const int wid  = t >> 5;

    if (r == 7) {
        // ---------------- embed copy ----------------
        const int c1 = counts.y;
        const int base = e * 1024 + wid * 128;
        if (base >= c1) return;
        for (int q = 0; q < 128; q += 4) {
            int2 pr[4]; float4 v[4]; bool ok[4];
            #pragma unroll
            for (int j = 0; j < 4; ++j) {
                const int idx = base + q + j;
                ok[j] = idx < c1;
                if (ok[j]) {
                    pr[j] = g_list1[idx];
                    v[j] = ((const float4*)(table + (size_t)pr[j].y * EMBED))[lane];
                }
            }
            #pragma unroll
            for (int j = 0; j < 4; ++j)
                if (ok[j])
                    ((float4*)(out + (size_t)pr[j].x * EMBED))[lane] = v[j];
        }
        return;
    }

    // ---------------- GEMM tile ----------------
    __shared__ uint4 sAH[512], sAL[512];       // 8KB each
    __shared__ uint2 sBH[1024], sBL[1024];     // 8KB each
    __shared__ int   s_cidx[TILE_M];
    __shared__ int   s_ridx[TILE_M];

    const int c0 = counts.x;
    const int go = 7 * e + r;
    const int m0 = go * TILE_M;
    if (m0 >= c0) return;
    const int rows = min(TILE_M, c0 - m0);

    const int warp_m = wid >> 2;     // 0..1
    const int warp_n = wid & 3;      // 0..3

    if (t < TILE_M) {
        const int src = (t < rows) ? (m0 + t) : m0;
        int2 pr = g_list0[src];
        s_cidx[t] = pr.x;
        s_ridx[t] = pr.y;
    }
    __syncthreads();

    const int tidf = t & 31;
    const int sg   = tidf >> 2;
    const int stc  = tidf & 3;
    const int tmA  = t >> 5;

    const int ra0 = tmA * 16 + sg;
    const int ra1 = ra0 + 8;
    const float* ap0 = feat0 + (size_t)s_ridx[ra0] * D_IN;
    const float* ap1 = feat0 + (size_t)s_ridx[ra1] * D_IN;

    float acc[4][4][4];
    #pragma unroll
    for (int a = 0; a < 4; ++a)
        #pragma unroll
        for (int bb = 0; bb < 4; ++bb)
            #pragma unroll
            for (int c = 0; c < 4; ++c) acc[a][bb][c] = 0.0f;

    for (int kk = 0; kk < D_IN; kk += KCHUNK) {
        if (kk) __syncthreads();

        // ---- stage A: gather + hi/lo split into fragment order ----
        #pragma unroll
        for (int tk = 0; tk < 2; ++tk) {
            const int k0 = kk + tk * 16 + stc * 2;
            float2 f00 = *(const float2*)(ap0 + k0);
            float2 f10 = *(const float2*)(ap1 + k0);
            float2 f01 = *(const float2*)(ap0 + k0 + 8);
            float2 f11 = *(const float2*)(ap1 + k0 + 8);
            uint4 H, L;
            split2(f00.x, f00.y, H.x, L.x);
            split2(f10.x, f10.y, H.y, L.y);
            split2(f01.x, f01.y, H.z, L.z);
            split2(f11.x, f11.y, H.w, L.w);
            const int idx = (tmA * 2 + tk) * 32 + tidf;
            sAH[idx] = H;
            sAL[idx] = L;
        }

        // ---- stage B: straight copy of pre-split W0 fragments ----
        {
            const uint4* gbh = (const uint4*)(g_BH + (kk >> 4) * 512);
            const uint4* gbl = (const uint4*)(g_BL + (kk >> 4) * 512);
            uint4* sbh = (uint4*)sBH;
            uint4* sbl = (uint4*)sBL;
            sbh[t]       = gbh[t];
            sbh[t + 256] = gbh[t + 256];
            sbl[t]       = gbl[t];
            sbl[t + 256] = gbl[t + 256];
        }
        __syncthreads();

        // ---- mma: 2 k-steps x (4 mt x 4 nt) x 3 passes ----
        #pragma unroll
        for (int ks = 0; ks < 2; ++ks) {
            uint2 bh[4], bl[4];
            #pragma unroll
            for (int nt = 0; nt < 4; ++nt) {
                const int idx = (ks * 16 + warp_n * 4 + nt) * 32 + lane;
                bh[nt] = sBH[idx];
                bl[nt] = sBL[idx];
            }
            #pragma unroll
            for (int mt = 0; mt < 4; ++mt) {
                const int idx = ((warp_m * 4 + mt) * 2 + ks) * 32 + lane;
                uint4 ah = sAH[idx];
                uint4 al = sAL[idx];
                #pragma unroll
                for (int nt = 0; nt < 4; ++nt) {
                    mma16816(acc[mt][nt], ah, bh[nt]);
                    mma16816(acc[mt][nt], al, bh[nt]);
                    mma16816(acc[mt][nt], ah, bl[nt]);
                }
            }
        }
    }

    // ---- epilogue: scatter from fragment layout ----
    const int g  = lane >> 2;
    const int tc = lane & 3;
    #pragma unroll
    for (int mt = 0; mt < 4; ++mt) {
        const int row0 = warp_m * 64 + mt * 16 + g;
        const int row1 = row0 + 8;
        float* o0 = (row0 < rows) ? (out + (size_t)s_cidx[row0] * EMBED) : nullptr;
        float* o1 = (row1 < rows) ? (out + (size_t)s_cidx[row1] * EMBED) : nullptr;
        #pragma unroll
        for (int nt = 0; nt < 4; ++nt) {
            const int col = warp_n * 32 + nt * 8 + tc * 2;
            if (o0) *(float2*)(o0 + col) = make_float2(acc[mt][nt][0], acc[mt][nt][1]);
            if (o1) *(float2*)(o1 + col) = make_float2(acc[mt][nt][2], acc[mt][nt][3]);
        }
    }
}

// ---------------------------------------------------------------------------
extern "C" void kernel_launch(void* const* d_in, const int* in_sizes, int n_in,
                              void* d_out, int out_size)
{
    const void*  node_ids    = d_in[0];
    const void*  node_tids   = d_in[1];
    const void*  type_ids    = d_in[2];
    const float* feat0       = (const float*)d_in[3];
    const float* W0          = (const float*)d_in[4];
    const float* embed_table = (const float*)d_in[5];
    float* out = (float*)d_out;

    const int N = in_sizes[0];

    const int cblocks = (N + 255) / 256;
    const int gridA   = cblocks + 4;
    kA<<<gridA, 256>>>(node_ids, node_tids, type_ids, W0, N, cblocks, gridA);

    const int gemmNeeded = (N + TILE_M - 1) / TILE_M;
    const int gridB = (gemmNeeded * 8 + 6) / 7 + 8;   // 1-in-8 blocks do embed
    kB<<<gridB, 256>>>(feat0, embed_table, out);
}

// round 5
// speedup vs baseline: 1.3064x; 1.3064x over previous
#include <cuda_runtime.h>
#include <cuda_bf16.h>
#include <cstdint>

// ---------------------------------------------------------------------------
// RelGraphEmbedLayer:
//   out[i] = feat0[type_ids[i]] @ W0           if node_tids[i] == 0
//   out[i] = node_embed_table[node_ids[i]]      if node_tids[i] == 1
//
// kA: compaction into payload lists + W0 -> tf32 fragment pre-pack
// kB: fused single-pass tf32 mma.sync GEMM + embedding copy (1-in-8 blocks)
// ---------------------------------------------------------------------------

#define D_IN   256
#define EMBED  128
#define TILE_M 128

__device__ int  g_c0, g_c1, g_arrA;
__device__ int2 g_final;
__device__ int2 g_list0[1100000];     // (dst_row, feat0_row)
__device__ int2 g_list1[1100000];     // (dst_row, node_id)
// tf32 B fragments: [ktile(32)][tn(16)][lane(32)] -> uint2 {b0,b1}
__device__ uint2 g_Btf[16384];        // 128 KB

__device__ __forceinline__ long long load_idx(const void* p, int i, int is64) {
    if (is64) return ((const long long*)p)[i];
    return (long long)((const int*)p)[i];
}

__device__ __forceinline__ unsigned cvt_tf32(float x) {
    unsigned u;
    asm("cvt.rna.tf32.f32 %0, %1;" : "=r"(u) : "f"(x));
    return u;
}

__device__ __forceinline__ void mma_tf32(float* d, const uint4& a, const uint2& b) {
    asm volatile(
        "mma.sync.aligned.m16n8k8.row.col.f32.tf32.tf32.f32 "
        "{%0,%1,%2,%3}, {%4,%5,%6,%7}, {%8,%9}, {%0,%1,%2,%3};"
        : "+f"(d[0]), "+f"(d[1]), "+f"(d[2]), "+f"(d[3])
        : "r"(a.x), "r"(a.y), "r"(a.z), "r"(a.w), "r"(b.x), "r"(b.y));
}

// ---------------------------------------------------------------------------
// kA: blocks [0, cblocks): compaction. blocks [cblocks, cblocks+4): W0 pack.
// Last block publishes counts to g_final and zeroes counters (self-reset).
// ---------------------------------------------------------------------------
__global__ __launch_bounds__(256) void kA(
    const void* __restrict__ node_ids,
    const void* __restrict__ node_tids,
    const void* __restrict__ type_ids,
    const float* __restrict__ W0,
    int N, int cblocks, int gridTotal)
{
    const int b = blockIdx.x;
    const int t = threadIdx.x;

    if (b >= cblocks) {
        // ---- W0 -> tf32 fragments in m16n8k8 B order ----
        const int wb = b - cblocks;
        for (int f = wb * 256 + t; f < 16384; f += 1024) {
            const int kt  = f >> 9;          // ktile of 8
            const int tn  = (f >> 5) & 15;   // n tile of 8
            const int ln  = f & 31;
            const int sg  = ln >> 2;         // n offset
            const int stc = ln & 3;          // k offset
            const int col = tn * 8 + sg;
            float b0 = W0[(size_t)(kt * 8 + stc) * EMBED + col];
            float b1 = W0[(size_t)(kt * 8 + stc + 4) * EMBED + col];
            uint2 v;
            v.x = cvt_tf32(b0);
            v.y = cvt_tf32(b1);
            g_Btf[f] = v;
        }
    } else {
        // ---- compaction with payloads ----
        const unsigned* w = (const unsigned*)node_ids;
        int is64 = 1;
        #pragma unroll
        for (int k = 0; k < 8; ++k)
            if (w[2 * k + 1] != 0u) { is64 = 0; break; }

        const int i    = b * 256 + t;
        const int lane = t & 31;
        const bool valid = i < N;
        long long tv = valid ? load_idx(node_tids, i, is64) : -1;
        const bool is0 = valid && (tv == 0);
        const bool is1 = valid && (tv != 0);

        unsigned m0 = __ballot_sync(0xffffffffu, is0);
        unsigned m1 = __ballot_sync(0xffffffffu, is1);
        int r0 = __popc(m0 & ((1u << lane) - 1u));
        int r1 = __popc(m1 & ((1u << lane) - 1u));
        int b0 = 0, b1 = 0;
        if (lane == 0) {
            if (m0) b0 = atomicAdd(&g_c0, __popc(m0));
            if (m1) b1 = atomicAdd(&g_c1, __popc(m1));
        }
        b0 = __shfl_sync(0xffffffffu, b0, 0);
        b1 = __shfl_sync(0xffffffffu, b1, 0);
        if (is0) {
            int2 e; e.x = i; e.y = (int)load_idx(type_ids, i, is64);
            g_list0[b0 + r0] = e;
        }
        if (is1) {
            int2 e; e.x = i; e.y = (int)load_idx(node_ids, i, is64);
            g_list1[b1 + r1] = e;
        }
    }

    __syncthreads();
    if (t == 0) {
        __threadfence();
        int old = atomicAdd(&g_arrA, 1);
        if (old == gridTotal - 1) {
            int2 f;
            f.x = atomicAdd(&g_c0, 0);
            f.y = atomicAdd(&g_c1, 0);
            g_final = f;
            g_c0 = 0;
            g_c1 = 0;
            g_arrA = 0;
            __threadfence();
        }
    }
}

// ---------------------------------------------------------------------------
// kB: blockIdx % 8 == 7 -> embed-copy block; else GEMM tile.
// GEMM: 128x128x256 tile, 8 warps (warp_m 0..1 x warp_n 0..3), warp 64x32,
// single-pass tf32 mma, A double-buffered smem fragments, B direct LDG.
// ---------------------------------------------------------------------------
__global__ __launch_bounds__(256, 2) void kB(
    const float* __restrict__ feat0,
    const float* __restrict__ table,
    float* __restrict__ out)
{
    const int2 counts = g_final;
    const int b = blockIdx.x;
    const int t = threadIdx.x;
    const int e = b >> 3;
    const int r = b & 7;
    const int lane = t & 31;
    const int wid  = t >> 5;

    if (r == 7) {
        // ---------------- embed copy ----------------
        const int c1 = counts.y;
        const int base = e * 1024 + wid * 128;
        if (base >= c1) return;
        for (int q = 0; q < 128; q += 4) {
            int2 pr[4]; float4 v[4]; bool ok[4];
            #pragma unroll
            for (int j = 0; j < 4; ++j) {
                const int idx = base + q + j;
                ok[j] = idx < c1;
                if (ok[j]) {
                    pr[j] = g_list1[idx];
                    v[j] = ((const float4*)(table + (size_t)pr[j].y * EMBED))[lane];
                }
            }
            #pragma unroll
            for (int j = 0; j < 4; ++j)
                if (ok[j])
                    ((float4*)(out + (size_t)pr[j].x * EMBED))[lane] = v[j];
        }
        return;
    }

    // ---------------- GEMM tile ----------------
    // A fragments, double buffered: [buf][tm(8)*4ks + ks][lane] uint4
    __shared__ uint4 sA[2][1024];      // 32 KB
    __shared__ int   s_cidx[TILE_M];
    __shared__ int   s_ridx[TILE_M];

    const int c0 = counts.x;
    const int go = 7 * e + r;
    const int m0 = go * TILE_M;
    if (m0 >= c0) return;
    const int rows = min(TILE_M, c0 - m0);

    const int warp_m = wid >> 1 >> 1;  // wid>>2: 0..1
    const int warp_n = wid & 3;        // 0..3

    if (t < TILE_M) {
        const int src = (t < rows) ? (m0 + t) : m0;
        int2 pr = g_list0[src];
        s_cidx[t] = pr.x;
        s_ridx[t] = pr.y;
    }
    __syncthreads();

    // staging identity: thread owns cols (stc mod 4) of rows r0, r1
    const int tm  = t >> 5;            // 0..7
    const int sg  = lane >> 2;
    const int stc = lane & 3;
    const float* ap0 = feat0 + (size_t)s_ridx[tm * 16 + sg] * D_IN + stc;
    const float* ap1 = feat0 + (size_t)s_ridx[tm * 16 + sg + 8] * D_IN + stc;

    float acc[4][4][4];
    #pragma unroll
    for (int a = 0; a < 4; ++a)
        #pragma unroll
        for (int bb = 0; bb < 4; ++bb)
            #pragma unroll
            for (int c = 0; c < 4; ++c) acc[a][bb][c] = 0.0f;

    // prefetch chunk 0 and stage it; prefetch chunk 1
    float f0[8], f1[8], n0[8], n1[8];
    #pragma unroll
    for (int j = 0; j < 8; ++j) {
        f0[j] = ap0[4 * j];
        f1[j] = ap1[4 * j];
    }
    #pragma unroll
    for (int ks = 0; ks < 4; ++ks) {
        uint4 fr;
        fr.x = cvt_tf32(f0[2 * ks]);
        fr.y = cvt_tf32(f1[2 * ks]);
        fr.z = cvt_tf32(f0[2 * ks + 1]);
        fr.w = cvt_tf32(f1[2 * ks + 1]);
        sA[0][(tm * 4 + ks) * 32 + lane] = fr;
    }
    #pragma unroll
    for (int j = 0; j < 8; ++j) {
        n0[j] = ap0[32 + 4 * j];
        n1[j] = ap1[32 + 4 * j];
    }
    __syncthreads();

    #pragma unroll
    for (int c = 0; c < 8; ++c) {
        const int buf = c & 1;

        // ---- mma over chunk c ----
        #pragma unroll
        for (int ks = 0; ks < 4; ++ks) {
            uint2 bb[4];
            #pragma unroll
            for (int nt = 0; nt < 4; ++nt)
                bb[nt] = g_Btf[(c * 4 + ks) * 512 + (warp_n * 4 + nt) * 32 + lane];
            #pragma unroll
            for (int mt = 0; mt < 4; ++mt) {
                uint4 a = sA[buf][((warp_m * 4 + mt) * 4 + ks) * 32 + lane];
                #pragma unroll
                for (int nt = 0; nt < 4; ++nt)
                    mma_tf32(acc[mt][nt], a, bb[nt]);
            }
        }

        // ---- stage chunk c+1 into other buffer; prefetch chunk c+2 ----
        if (c < 7) {
            #pragma unroll
            for (int ks = 0; ks < 4; ++ks) {
                uint4 fr;
                fr.x = cvt_tf32(n0[2 * ks]);
                fr.y = cvt_tf32(n1[2 * ks]);
                fr.z = cvt_tf32(n0[2 * ks + 1]);
                fr.w = cvt_tf32(n1[2 * ks + 1]);
                sA[buf ^ 1][(tm * 4 + ks) * 32 + lane] = fr;
            }
            if (c < 6) {
                #pragma unroll
                for (int j = 0; j < 8; ++j) {
                    n0[j] = ap0[32 * (c + 2) + 4 * j];
                    n1[j] = ap1[32 * (c + 2) + 4 * j];
                }
            }
        }
        __syncthreads();
    }

    // ---- epilogue: scatter from fragment layout ----
    const int g  = lane >> 2;
    const int tc = lane & 3;
    #pragma unroll
    for (int mt = 0; mt < 4; ++mt) {
        const int row0 = warp_m * 64 + mt * 16 + g;
        const int row1 = row0 + 8;
        float* o0 = (row0 < rows) ? (out + (size_t)s_cidx[row0] * EMBED) : nullptr;
        float* o1 = (row1 < rows) ? (out + (size_t)s_cidx[row1] * EMBED) : nullptr;
        #pragma unroll
        for (int nt = 0; nt < 4; ++nt) {
            const int col = warp_n * 32 + nt * 8 + tc * 2;
            if (o0) *(float2*)(o0 + col) = make_float2(acc[mt][nt][0], acc[mt][nt][1]);
            if (o1) *(float2*)(o1 + col) = make_float2(acc[mt][nt][2], acc[mt][nt][3]);
        }
    }
}

// ---------------------------------------------------------------------------
extern "C" void kernel_launch(void* const* d_in, const int* in_sizes, int n_in,
                              void* d_out, int out_size)
{
    const void*  node_ids    = d_in[0];
    const void*  node_tids   = d_in[1];
    const void*  type_ids    = d_in[2];
    const float* feat0       = (const float*)d_in[3];
    const float* W0          = (const float*)d_in[4];
    const float* embed_table = (const float*)d_in[5];
    float* out = (float*)d_out;

    const int N = in_sizes[0];

    const int cblocks = (N + 255) / 256;
    const int gridA   = cblocks + 4;
    kA<<<gridA, 256>>>(node_ids, node_tids, type_ids, W0, N, cblocks, gridA);

    const int gemmNeeded = (N + TILE_M - 1) / TILE_M;
    const int gridB = (gemmNeeded * 8 + 6) / 7 + 8;   // 1-in-8 blocks do embed
    kB<<<gridB, 256>>>(feat0, embed_table, out);
}